// round 8
// baseline (speedup 1.0000x reference)
#include <cuda_runtime.h>
#include <cuda_bf16.h>
#include <math.h>

// FFMCell: new_state = state * gamma(t) + x, gamma = exp((-|a| + i b) * t)
// T=4096, TRACE=64, CTX=64.
//
// R8: single fused kernel, grid = T, 256 threads, 4 float4-groups/thread.
// Register-free software pipeline: at block start each thread issues
// prefetch.global.L2 for ALL its data (16 lines), so DRAM streams from
// cycle 0 with zero data registers held. Then the factor prologue
// (64 sincos + 64 exp per 4096 elements) + one barrier execute under the
// prefetch stream. The main loop's loads hit L2, compute, and store with
// streaming (__stcs) stores. ~40 regs -> 6 blocks/SM (75% occ).

__global__ void __launch_bounds__(256, 6) ffm_pf_kernel(
    const float4* __restrict__ sre,
    const float4* __restrict__ sim,
    const float4* __restrict__ xre,
    const float4* __restrict__ xim,
    const float* __restrict__ a,
    const float* __restrict__ b,
    const int* __restrict__ ivec,
    const int* __restrict__ jvec,
    float* __restrict__ out,
    float* __restrict__ out_tail)
{
    const int t   = blockIdx.x;
    const int tid = threadIdx.x;

    __shared__ float  s_dec[64];
    __shared__ float2 s_cs[64];             // (cos, sin) per ctx

    const int g0 = t * 1024 + tid;          // first float4-group

    // ---- Phase 0: register-free L2 prefetch of the whole block tile ------
    #pragma unroll
    for (int it = 0; it < 4; ++it) {
        const int g = g0 + it * 256;
        asm volatile("prefetch.global.L2 [%0];" :: "l"(sre + g));
        asm volatile("prefetch.global.L2 [%0];" :: "l"(sim + g));
        asm volatile("prefetch.global.L2 [%0];" :: "l"(xre + g));
        asm volatile("prefetch.global.L2 [%0];" :: "l"(xim + g));
    }

    // ---- Phase 1: per-tile factors (under the prefetch stream) -----------
    if (tid < 64) {
        const float tf = (float)__ldg(&jvec[t]);
        const float th = __ldg(&b[tid]) * tf;   // same fp32 product as ref
        float sn, cs;
        sincosf(th, &sn, &cs);
        s_cs[tid] = make_float2(cs, sn);
    } else if (tid < 128) {
        const float tf = (float)__ldg(&jvec[t]);
        s_dec[tid - 64] = expf(-fabsf(__ldg(&a[tid - 64])) * tf);
    } else if (tid == 128 && out_tail != nullptr) {
        out_tail[t] = (float)(__ldg(&jvec[t]) + __ldg(&ivec[t]));
    }
    __syncthreads();

    // Loop-invariant per-thread cos/sin (this thread's 4 ctx columns).
    const float4* s_cs4 = reinterpret_cast<const float4*>(s_cs);
    const int cbase = (tid & 15) << 1;
    const float4 csA = s_cs4[cbase];        // (cos0,sin0,cos1,sin1)
    const float4 csB = s_cs4[cbase + 1];    // (cos2,sin2,cos3,sin3)

    float4* __restrict__ out4 = reinterpret_cast<float4*>(out);
    const int tr0 = tid >> 4;               // local trace row of iter 0

    // ---- Phase 2: compute + streaming store over 4 iterations ------------
    #pragma unroll
    for (int it = 0; it < 4; ++it) {
        const int g = g0 + it * 256;

        const float4 sr = __ldcs(&sre[g]);
        const float4 si = __ldcs(&sim[g]);
        const float4 xr = __ldcs(&xre[g]);
        const float4 xi = __ldcs(&xim[g]);

        const float dec = s_dec[it * 16 + tr0];

        const float gr0 = dec * csA.x, gi0 = dec * csA.y;
        const float gr1 = dec * csA.z, gi1 = dec * csA.w;
        const float gr2 = dec * csB.x, gi2 = dec * csB.y;
        const float gr3 = dec * csB.z, gi3 = dec * csB.w;

        float4 o0, o1;
        o0.x = fmaf(sr.x, gr0, fmaf(-si.x, gi0, xr.x));
        o0.y = fmaf(sr.x, gi0, fmaf( si.x, gr0, xi.x));
        o0.z = fmaf(sr.y, gr1, fmaf(-si.y, gi1, xr.y));
        o0.w = fmaf(sr.y, gi1, fmaf( si.y, gr1, xi.y));
        o1.x = fmaf(sr.z, gr2, fmaf(-si.z, gi2, xr.z));
        o1.y = fmaf(sr.z, gi2, fmaf( si.z, gr2, xi.z));
        o1.z = fmaf(sr.w, gr3, fmaf(-si.w, gi3, xr.w));
        o1.w = fmaf(sr.w, gi3, fmaf( si.w, gr3, xi.w));

        __stcs(&out4[2 * g],     o0);
        __stcs(&out4[2 * g + 1], o1);
    }
}

extern "C" void kernel_launch(void* const* d_in, const int* in_sizes, int n_in,
                              void* d_out, int out_size)
{
    const float4* sre = (const float4*)d_in[0];
    const float4* sim = (const float4*)d_in[1];
    const float4* xre = (const float4*)d_in[2];
    const float4* xim = (const float4*)d_in[3];
    const float*  a   = (const float*)d_in[4];
    const float*  b   = (const float*)d_in[5];
    const int*    iv  = (const int*)d_in[6];
    const int*    jv  = (const int*)d_in[7];

    const int T = in_sizes[6];                      // 4096
    const long long N = (long long)in_sizes[0];     // T*TRACE*CTX

    float* out = (float*)d_out;
    float* out_tail = nullptr;
    if ((long long)out_size > 2LL * N) {
        out_tail = out + 2LL * N;
    }

    ffm_pf_kernel<<<T, 256>>>(sre, sim, xre, xim, a, b, iv, jv,
                              out, out_tail);
}

// round 9
// speedup vs baseline: 1.0440x; 1.0440x over previous
#include <cuda_runtime.h>
#include <cuda_bf16.h>
#include <math.h>

// FFMCell: new_state = state * gamma(t) + x, gamma = exp((-|a| + i b) * t)
// T=4096, TRACE=64, CTX=64.
//
// R9: single fused kernel, grid = T, 256 threads, 4 float4-groups/thread.
// Register-dieted software pipeline: only the state streams (sre/sim) are
// prefetched one iteration ahead (8 regs); x is loaded just-in-time and
// consumed LAST (o = (s*g) + x, reassociated) so its latency is hidden by
// the FMA chain + occupancy. Full factor amortization (64 sincos + 64 exp
// per 4096 elements), one barrier per block. 51-reg cap -> 5 blocks/SM.

__global__ void __launch_bounds__(256, 5) ffm_r9_kernel(
    const float4* __restrict__ sre,
    const float4* __restrict__ sim,
    const float4* __restrict__ xre,
    const float4* __restrict__ xim,
    const float* __restrict__ a,
    const float* __restrict__ b,
    const int* __restrict__ ivec,
    const int* __restrict__ jvec,
    float* __restrict__ out,
    float* __restrict__ out_tail)
{
    const int t   = blockIdx.x;
    const int tid = threadIdx.x;

    __shared__ float  s_dec[64];
    __shared__ float2 s_cs[64];             // (cos, sin) per ctx

    const int g0 = t * 1024 + tid;          // first float4-group

    // ---- Phase 0: iter-0 state loads in flight before the prologue -------
    float4 sr = __ldcs(&sre[g0]);
    float4 si = __ldcs(&sim[g0]);

    // ---- Phase 1: per-tile factors ---------------------------------------
    if (tid < 64) {
        const float tf = (float)__ldg(&jvec[t]);
        const float th = __ldg(&b[tid]) * tf;   // same fp32 product as ref
        float sn, cs;
        sincosf(th, &sn, &cs);
        s_cs[tid] = make_float2(cs, sn);
    } else if (tid < 128) {
        const float tf = (float)__ldg(&jvec[t]);
        s_dec[tid - 64] = expf(-fabsf(__ldg(&a[tid - 64])) * tf);
    } else if (tid == 128 && out_tail != nullptr) {
        out_tail[t] = (float)(__ldg(&jvec[t]) + __ldg(&ivec[t]));
    }
    __syncthreads();

    // Loop-invariant per-thread cos/sin (this thread's 4 ctx columns).
    const float4* s_cs4 = reinterpret_cast<const float4*>(s_cs);
    const int cbase = (tid & 15) << 1;
    const float4 csA = s_cs4[cbase];        // (cos0,sin0,cos1,sin1)
    const float4 csB = s_cs4[cbase + 1];    // (cos2,sin2,cos3,sin3)

    float4* __restrict__ out4 = reinterpret_cast<float4*>(out);
    const int tr0 = tid >> 4;               // local trace row of iter 0

    #pragma unroll
    for (int it = 0; it < 4; ++it) {
        const int g = g0 + it * 256;

        // JIT x loads for THIS iteration (consumed last in the FMA tree).
        const float4 xr = __ldcs(&xre[g]);
        const float4 xi = __ldcs(&xim[g]);

        // Prefetch next iteration's state (held across compute: 8 regs).
        float4 nsr, nsi;
        if (it < 3) {
            nsr = __ldcs(&sre[g + 256]);
            nsi = __ldcs(&sim[g + 256]);
        }

        const float dec = s_dec[it * 16 + tr0];

        const float gr0 = dec * csA.x, gi0 = dec * csA.y;
        const float gr1 = dec * csA.z, gi1 = dec * csA.w;
        const float gr2 = dec * csB.x, gi2 = dec * csB.y;
        const float gr3 = dec * csB.z, gi3 = dec * csB.w;

        // p = s * g  (x-free FMA chain runs while x is in flight)
        float4 p0, p1;
        p0.x = fmaf(sr.x, gr0, -si.x * gi0);
        p0.y = fmaf(sr.x, gi0,  si.x * gr0);
        p0.z = fmaf(sr.y, gr1, -si.y * gi1);
        p0.w = fmaf(sr.y, gi1,  si.y * gr1);
        p1.x = fmaf(sr.z, gr2, -si.z * gi2);
        p1.y = fmaf(sr.z, gi2,  si.z * gr2);
        p1.z = fmaf(sr.w, gr3, -si.w * gi3);
        p1.w = fmaf(sr.w, gi3,  si.w * gr3);

        float4 o0, o1;
        o0.x = p0.x + xr.x;  o0.y = p0.y + xi.x;
        o0.z = p0.z + xr.y;  o0.w = p0.w + xi.y;
        o1.x = p1.x + xr.z;  o1.y = p1.y + xi.z;
        o1.z = p1.z + xr.w;  o1.w = p1.w + xi.w;

        __stcs(&out4[2 * g],     o0);
        __stcs(&out4[2 * g + 1], o1);

        sr = nsr; si = nsi;
    }
}

extern "C" void kernel_launch(void* const* d_in, const int* in_sizes, int n_in,
                              void* d_out, int out_size)
{
    const float4* sre = (const float4*)d_in[0];
    const float4* sim = (const float4*)d_in[1];
    const float4* xre = (const float4*)d_in[2];
    const float4* xim = (const float4*)d_in[3];
    const float*  a   = (const float*)d_in[4];
    const float*  b   = (const float*)d_in[5];
    const int*    iv  = (const int*)d_in[6];
    const int*    jv  = (const int*)d_in[7];

    const int T = in_sizes[6];                      // 4096
    const long long N = (long long)in_sizes[0];     // T*TRACE*CTX

    float* out = (float*)d_out;
    float* out_tail = nullptr;
    if ((long long)out_size > 2LL * N) {
        out_tail = out + 2LL * N;
    }

    ffm_r9_kernel<<<T, 256>>>(sre, sim, xre, xim, a, b, iv, jv,
                              out, out_tail);
}